// round 2
// baseline (speedup 1.0000x reference)
#include <cuda_runtime.h>
#include <math.h>

#define B 8
#define N 4096
#define DF 768
#define K1 8
#define K2 2
#define DS 128
#define BK (B*K1)        // 64
#define NS (BK*K2)       // 128 slot rows
#define SCALE 0.088388347648318447f
#define EPS_SA 1e-8f
#define OBJ_SIZE (NS*DS)             // 16384 child_objects floats
// child_gating = NS * N floats after that

// ------------------- scratch (device globals; no allocations) -------------------
__device__ float g_mean[B*N];
__device__ float g_var[B*N];
__device__ float g_denom[BK];
__device__ float g_s[BK*N];
__device__ float g_slots[NS*DS];
__device__ __align__(16) float g_a[NS*DF];
__device__ float g_sumA[NS];
__device__ float g_beta[NS];
__device__ float g_accA[NS*DF];
__device__ float g_accZ[NS];
__device__ float g_accD[NS];
__device__ float g_cv[DS];

// ------------------- helpers -------------------
__device__ __forceinline__ float block_reduce_256(float v, float* red, int tid) {
    red[tid] = v; __syncthreads();
    #pragma unroll
    for (int h = 128; h > 0; h >>= 1) {
        if (tid < h) red[tid] += red[tid + h];
        __syncthreads();
    }
    float r = red[0];
    __syncthreads();
    return r;
}

// ------------------- one-time kernels -------------------
// per-token mean/var over DF.  grid: B*N/8 blocks of 256 (8 warps, warp/row)
__global__ void stats_kernel(const float* __restrict__ tokens) {
    int row  = blockIdx.x * 8 + (threadIdx.x >> 5);
    int lane = threadIdx.x & 31;
    const float4* xp = (const float4*)(tokens + (size_t)row * DF);
    float s = 0.f, s2 = 0.f;
    #pragma unroll
    for (int k = 0; k < 6; k++) {
        float4 v = xp[k*32 + lane];
        s  += v.x + v.y + v.z + v.w;
        s2 += v.x*v.x + v.y*v.y + v.z*v.z + v.w*v.w;
    }
    #pragma unroll
    for (int off = 16; off; off >>= 1) {
        s  += __shfl_xor_sync(0xffffffffu, s,  off);
        s2 += __shfl_xor_sync(0xffffffffu, s2, off);
    }
    if (lane == 0) {
        float m = s * (1.f/DF);
        g_mean[row] = m;
        g_var[row]  = s2 * (1.f/DF) - m*m;
    }
}

// per-(b,k1) mean of parent mask over N. grid BK, block 256
__global__ void denom_kernel(const float* __restrict__ masks) {
    __shared__ float red[256];
    int bk = blockIdx.x, tid = threadIdx.x;
    float s = 0.f;
    for (int j = tid; j < N; j += 256) s += masks[(size_t)bk*N + j];
    float tot = block_reduce_256(s, red, tid);
    if (tid == 0) g_denom[bk] = tot * (1.f/N);
}

// s[b,k1,j] = w / sqrt(w^2 * var + 1e-5)
__global__ void s_kernel(const float* __restrict__ masks) {
    int idx = blockIdx.x*256 + threadIdx.x;
    if (idx >= BK*N) return;
    int bk = idx / N;
    int b  = bk / K1;
    int j  = idx - bk*N;
    float denom = g_denom[bk];
    float w = (denom > 1e-6f) ? (masks[idx] / (denom + 1e-6f)) : 1.0f;
    float v = g_var[b*N + j];
    g_s[idx] = w * rsqrtf(w*w*v + 1e-5f);
}

__global__ void slots_init_kernel(const float* __restrict__ ps, const float* __restrict__ eps) {
    int idx = blockIdx.x*256 + threadIdx.x;
    if (idx >= NS*DS) return;
    int r = idx / DS, d = idx - r*DS;
    int bk = r >> 1;                 // K2 = 2
    g_slots[idx] = ps[bk*DS + d] + 0.01f * eps[idx];
}

// cv = Wv @ ln_in_b   (128 threads)
__global__ void cv_kernel(const float* __restrict__ Wv, const float* __restrict__ lnb) {
    int t = threadIdx.x;
    float acc = 0.f;
    for (int f = 0; f < DF; f++) acc += Wv[t*DF + f] * lnb[f];
    g_cv[t] = acc;
}

// ------------------- per-iteration kernels -------------------
// per slot row r: sn = LN(slots), q = sn@Wq^T, a = g ⊙ (Wk^T q), sumA, beta.
// grid NS blocks of 256
__global__ void qa_kernel(const float* __restrict__ Wq, const float* __restrict__ Wk,
                          const float* __restrict__ sg, const float* __restrict__ sb,
                          const float* __restrict__ ig, const float* __restrict__ ib) {
    __shared__ float sn[DS], q[DS], red[256];
    int r = blockIdx.x, tid = threadIdx.x;
    float val = (tid < DS) ? g_slots[r*DS + tid] : 0.f;
    float sum = block_reduce_256((tid < DS) ? val : 0.f, red, tid);
    float m = sum * (1.f/DS);
    float dv = (tid < DS) ? (val - m) : 0.f;
    float var = block_reduce_256(dv*dv, red, tid) * (1.f/DS);
    float rstd = rsqrtf(var + 1e-5f);
    if (tid < DS) sn[tid] = dv * rstd * sg[tid] + sb[tid];
    __syncthreads();
    if (tid < DS) {
        float acc = 0.f;
        #pragma unroll 8
        for (int f = 0; f < DS; f++) acc += Wq[tid*DS + f] * sn[f];
        q[tid] = acc;
    }
    __syncthreads();
    float psum = 0.f, pbeta = 0.f;
    for (int f = tid; f < DF; f += 256) {
        float raw = 0.f;
        #pragma unroll 8
        for (int c = 0; c < DS; c++) raw += Wk[c*DF + f] * q[c];
        float a = raw * ig[f];
        g_a[r*DF + f] = a;
        psum  += a;
        pbeta += raw * ib[f];
    }
    float tsum  = block_reduce_256(psum, red, tid);
    float tbeta = block_reduce_256(pbeta, red, tid);
    if (tid == 0) { g_sumA[r] = tsum; g_beta[r] = tbeta; }
}

__global__ void zero_kernel() {
    int idx = blockIdx.x*256 + threadIdx.x;
    if (idx < NS*DF) g_accA[idx] = 0.f;
    if (idx < NS) { g_accZ[idx] = 0.f; g_accD[idx] = 0.f; }
}

// Fused dots -> softmax(K2=2) -> attention accumulation, warp-per-token.
// grid = 32 tiles * 64 bk = 2048 blocks of 128 threads (4 warps, 32 tokens each).
__global__ void __launch_bounds__(128) big_kernel(const float* __restrict__ tokens,
                                                  const float* __restrict__ masks,
                                                  float* __restrict__ out, int last) {
    int bk   = blockIdx.x & 63;
    int tile = blockIdx.x >> 6;
    int b    = bk >> 3;
    int w    = threadIdx.x >> 5, lane = threadIdx.x & 31;
    int r0   = bk * 2;

    const float4* a0p = (const float4*)(g_a + (size_t)r0*DF);
    const float4* a1p = (const float4*)(g_a + (size_t)(r0+1)*DF);
    float4 a0v[6], a1v[6], acc0[6], acc1[6];
    #pragma unroll
    for (int k = 0; k < 6; k++) {
        a0v[k] = a0p[k*32 + lane];
        a1v[k] = a1p[k*32 + lane];
        acc0[k] = make_float4(0.f,0.f,0.f,0.f);
        acc1[k] = make_float4(0.f,0.f,0.f,0.f);
    }
    float sA0 = g_sumA[r0], sA1 = g_sumA[r0+1];
    float be0 = g_beta[r0], be1 = g_beta[r0+1];
    float z0 = 0.f, z1 = 0.f, dd0 = 0.f, dd1 = 0.f;
    float keep0 = 0.f, keep1 = 0.f;
    int j0 = tile*128 + w*32;

    for (int t = 0; t < 32; t++) {
        int j = j0 + t;
        const float4* xp = (const float4*)(tokens + (size_t)(b*N + j)*DF);
        float4 xv[6];
        #pragma unroll
        for (int k = 0; k < 6; k++) xv[k] = xp[k*32 + lane];
        float d0 = 0.f, d1 = 0.f;
        #pragma unroll
        for (int k = 0; k < 6; k++) {
            d0 += a0v[k].x*xv[k].x + a0v[k].y*xv[k].y + a0v[k].z*xv[k].z + a0v[k].w*xv[k].w;
            d1 += a1v[k].x*xv[k].x + a1v[k].y*xv[k].y + a1v[k].z*xv[k].z + a1v[k].w*xv[k].w;
        }
        #pragma unroll
        for (int off = 16; off; off >>= 1) {
            d0 += __shfl_xor_sync(0xffffffffu, d0, off);
            d1 += __shfl_xor_sync(0xffffffffu, d1, off);
        }
        float s = g_s[(size_t)bk*N + j];
        float m = g_mean[b*N + j];
        float q0 = SCALE * (s*(d0 - m*sA0) + be0);
        float q1 = SCALE * (s*(d1 - m*sA1) + be1);
        float mx = fmaxf(q0, q1);
        float e0 = __expf(q0 - mx), e1 = __expf(q1 - mx);
        float inv = 1.f / (e0 + e1);
        float at0 = e0*inv + EPS_SA, at1 = e1*inv + EPS_SA;
        if (t == lane) { keep0 = at0; keep1 = at1; }
        float c0 = at0 * s, c1 = at1 * s;
        z0 += at0; z1 += at1; dd0 += c0*m; dd1 += c1*m;
        #pragma unroll
        for (int k = 0; k < 6; k++) {
            acc0[k].x += c0*xv[k].x; acc0[k].y += c0*xv[k].y;
            acc0[k].z += c0*xv[k].z; acc0[k].w += c0*xv[k].w;
            acc1[k].x += c1*xv[k].x; acc1[k].y += c1*xv[k].y;
            acc1[k].z += c1*xv[k].z; acc1[k].w += c1*xv[k].w;
        }
    }

    if (last) {   // child_gating = attn * parent_mask (final-iter attention)
        int j = j0 + lane;
        float mk = masks[(size_t)bk*N + j];
        out[OBJ_SIZE + (size_t)r0*N + j]     = keep0 * mk;
        out[OBJ_SIZE + (size_t)(r0+1)*N + j] = keep1 * mk;
    }

    __shared__ float shA[2*DF];
    for (int i = threadIdx.x; i < 2*DF; i += 128) shA[i] = 0.f;
    __syncthreads();
    #pragma unroll
    for (int k = 0; k < 6; k++) {
        int f = (k*32 + lane)*4;
        atomicAdd(&shA[f],      acc0[k].x); atomicAdd(&shA[f+1],    acc0[k].y);
        atomicAdd(&shA[f+2],    acc0[k].z); atomicAdd(&shA[f+3],    acc0[k].w);
        atomicAdd(&shA[DF+f],   acc1[k].x); atomicAdd(&shA[DF+f+1], acc1[k].y);
        atomicAdd(&shA[DF+f+2], acc1[k].z); atomicAdd(&shA[DF+f+3], acc1[k].w);
    }
    __syncthreads();
    for (int i = threadIdx.x; i < 2*DF; i += 128)
        atomicAdd(&g_accA[(size_t)r0*DF + i], shA[i]);
    if (lane == 0) {
        atomicAdd(&g_accZ[r0],   z0); atomicAdd(&g_accZ[r0+1], z1);
        atomicAdd(&g_accD[r0],  dd0); atomicAdd(&g_accD[r0+1], dd1);
    }
}

// per slot row: updates = Wv(g*(A-D))/Z + cv  -> GRU -> LN -> MLP.  grid NS blocks of 128
__global__ void upd_kernel(const float* __restrict__ Wv,  const float* __restrict__ ig,
                           const float* __restrict__ Wih, const float* __restrict__ Whh,
                           const float* __restrict__ bih, const float* __restrict__ bhh,
                           const float* __restrict__ mg,  const float* __restrict__ mb,
                           const float* __restrict__ W1,  const float* __restrict__ b1,
                           const float* __restrict__ W2,  const float* __restrict__ b2,
                           float* __restrict__ out, int last) {
    __shared__ float gv[DF];
    __shared__ float su[DS], sh[DS], shh[DS];
    __shared__ float sy[4*DS];
    __shared__ float red[DS];
    int r = blockIdx.x, t = threadIdx.x;
    float D = g_accD[r], Z = g_accZ[r];
    for (int f = t; f < DF; f += DS) gv[f] = ig[f] * (g_accA[(size_t)r*DF + f] - D);
    float hprev = g_slots[r*DS + t];
    sh[t] = hprev;
    __syncthreads();
    float acc = 0.f;
    #pragma unroll 8
    for (int f = 0; f < DF; f++) acc += Wv[t*DF + f] * gv[f];
    su[t] = acc / Z + g_cv[t];
    __syncthreads();
    // GRU
    float gi0 = bih[t], gi1 = bih[DS+t], gi2 = bih[2*DS+t];
    float gh0 = bhh[t], gh1 = bhh[DS+t], gh2 = bhh[2*DS+t];
    #pragma unroll 4
    for (int f = 0; f < DS; f++) {
        float uf = su[f], hf = sh[f];
        gi0 += Wih[t*DS + f]*uf;
        gi1 += Wih[(DS+t)*DS + f]*uf;
        gi2 += Wih[(2*DS+t)*DS + f]*uf;
        gh0 += Whh[t*DS + f]*hf;
        gh1 += Whh[(DS+t)*DS + f]*hf;
        gh2 += Whh[(2*DS+t)*DS + f]*hf;
    }
    float rr = 1.f / (1.f + __expf(-(gi0 + gh0)));
    float zz = 1.f / (1.f + __expf(-(gi1 + gh1)));
    float nn = tanhf(gi2 + rr*gh2);
    float news = (1.f - zz)*nn + zz*hprev;
    // LN over 128 threads
    red[t] = news; __syncthreads();
    #pragma unroll
    for (int h2 = 64; h2; h2 >>= 1) { if (t < h2) red[t] += red[t+h2]; __syncthreads(); }
    float m = red[0] * (1.f/DS); __syncthreads();
    float dv = news - m;
    red[t] = dv*dv; __syncthreads();
    #pragma unroll
    for (int h2 = 64; h2; h2 >>= 1) { if (t < h2) red[t] += red[t+h2]; __syncthreads(); }
    float rstd = rsqrtf(red[0]*(1.f/DS) + 1e-5f); __syncthreads();
    shh[t] = dv*rstd*mg[t] + mb[t];
    __syncthreads();
    // MLP: gelu(h@W1^T+b1)@W2^T+b2  (exact gelu)
    #pragma unroll
    for (int oo = 0; oo < 4; oo++) {
        int o = oo*DS + t;
        float a2 = b1[o];
        #pragma unroll 4
        for (int f = 0; f < DS; f++) a2 += W1[o*DS + f]*shh[f];
        sy[o] = 0.5f * a2 * (1.f + erff(a2 * 0.70710678118654752f));
    }
    __syncthreads();
    float o2 = b2[t];
    #pragma unroll 8
    for (int o = 0; o < 4*DS; o++) o2 += W2[t*4*DS + o]*sy[o];
    g_slots[r*DS + t] = o2;
    if (last) out[r*DS + t] = o2;   // child_objects
}

// ------------------- launch -------------------
extern "C" void kernel_launch(void* const* d_in, const int* in_sizes, int n_in,
                              void* d_out, int out_size) {
    const float* tokens = (const float*)d_in[0];
    const float* pslots = (const float*)d_in[1];
    const float* masks  = (const float*)d_in[2];
    const float* eps    = (const float*)d_in[3];
    const float* ig     = (const float*)d_in[4];   // ln_in_g
    const float* ib     = (const float*)d_in[5];   // ln_in_b
    const float* sg     = (const float*)d_in[6];   // ln_s_g
    const float* sb     = (const float*)d_in[7];   // ln_s_b
    const float* Wq     = (const float*)d_in[8];
    const float* Wk     = (const float*)d_in[9];
    const float* Wv     = (const float*)d_in[10];
    const float* Wih    = (const float*)d_in[11];
    const float* Whh    = (const float*)d_in[12];
    const float* bih    = (const float*)d_in[13];
    const float* bhh    = (const float*)d_in[14];
    const float* mg     = (const float*)d_in[15];  // mlp_ln_g
    const float* mb     = (const float*)d_in[16];  // mlp_ln_b
    const float* W1     = (const float*)d_in[17];
    const float* b1     = (const float*)d_in[18];
    const float* W2     = (const float*)d_in[19];
    const float* b2     = (const float*)d_in[20];
    float* out = (float*)d_out;

    stats_kernel<<<B*N/8, 256>>>(tokens);
    denom_kernel<<<BK, 256>>>(masks);
    s_kernel<<<(BK*N + 255)/256, 256>>>(masks);
    slots_init_kernel<<<(NS*DS + 255)/256, 256>>>(pslots, eps);
    cv_kernel<<<1, DS>>>(Wv, ib);

    for (int it = 0; it < 3; it++) {
        int last = (it == 2);
        qa_kernel<<<NS, 256>>>(Wq, Wk, sg, sb, ig, ib);
        zero_kernel<<<(NS*DF + 255)/256, 256>>>();
        big_kernel<<<32*BK, 128>>>(tokens, masks, out, last);
        upd_kernel<<<NS, DS>>>(Wv, ig, Wih, Whh, bih, bhh, mg, mb,
                               W1, b1, W2, b2, out, last);
    }
}